// round 14
// baseline (speedup 1.0000x reference)
#include <cuda_runtime.h>
#include <cstdint>

#define CCH 256
#define HH 256
#define WW 256
#define PLANE (HH * WW)
#define TH 4
#define TW 32
#define HALO_ROWS 10              // TH + 6
#define HALO_W2 20                // staged float2 per row (40 floats)
#define HALO_N2 (HALO_ROWS * HALO_W2)  // 200 float2 per channel slab
#define SMW 44                    // y slab row stride in floats (conflict-free padding)
#define SMW2 (SMW / 2)            // 22 float2 stride
#define SLAB (HALO_ROWS * SMW)    // 440 floats per y slab
#define CPB 4                     // channels per barrier
#define NGRP (CCH / CPB)          // 64 groups
#define NSLOT 2                   // ceil(200 / 128) y staging slots per thread
#define NTHREADS 128
#define EPSF 1e-12f

__device__ __forceinline__ unsigned smem_u32(const void* p) {
    return (unsigned)__cvta_generic_to_shared(p);
}
__device__ __forceinline__ void cp_async8(unsigned dst, const void* src, unsigned sz) {
    asm volatile("cp.async.ca.shared.global [%0], [%1], 8, %2;\n"
                 :: "r"(dst), "l"(src), "r"(sz));
}
__device__ __forceinline__ void cp_commit() {
    asm volatile("cp.async.commit_group;\n");
}
__device__ __forceinline__ void cp_wait0() {
    asm volatile("cp.async.wait_group 0;\n");
}

__global__ __launch_bounds__(NTHREADS, 4)
void corr_kernel(const float* __restrict__ x,
                 const float* __restrict__ y,
                 float* __restrict__ out)
{
    __shared__ __align__(16) float sy[2][CPB][SLAB];

    const int tid = threadIdx.x;
    const int tx  = tid & 3;          // 0..3, each owns 8 w-pixels
    const int ty  = (tid >> 2) & 3;   // 0..3
    const int grp = tid >> 4;         // 0..7: vertical offset index (7 = staging-only)
    const bool comp = (grp < 7);
    const int b   = blockIdx.z;
    const int h0  = blockIdx.y * TH;
    const int w0  = blockIdx.x * TW;
    const int h   = h0 + ty;

    // ---- y staging slots: halo gy in [h0-3, h0+6], gx in [w0-4, w0+35], even gx
    int      g2of[NSLOT];   // global float2 offset
    int      d2of[NSLOT];   // slab float2 offset (stride 22 float2 per row)
    unsigned ssz[NSLOT];
    bool     wr[NSLOT];
    #pragma unroll
    for (int k = 0; k < NSLOT; k++) {
        int li = tid + k * NTHREADS;
        int r  = li / HALO_W2;
        int c2 = li - r * HALO_W2;
        int gy = h0 - 3 + r;
        int gx = w0 - 4 + 2 * c2;
        wr[k]  = li < HALO_N2;
        bool v = wr[k] && gy >= 0 && gy < HH && gx >= 0 && gx < WW;
        g2of[k] = v ? (gy * (WW / 2) + (gx >> 1)) : 0;
        d2of[k] = r * SMW2 + c2;
        ssz[k]  = v ? 8u : 0u;
    }

    // ---- x read direct from global, software-pipelined one channel ahead.
    //      Warps grp=0..6 share identical addresses -> L1 dedup after first toucher.
    const float4* xp = reinterpret_cast<const float4*>(
        x + (((size_t)b * CCH) * HH + h) * WW + w0 + tx * 8);
    const float2* yc = reinterpret_cast<const float2*>(y) +
        (size_t)b * CCH * (PLANE / 2);

    float acc[7][8];
    #pragma unroll
    for (int j = 0; j < 7; j++)
        #pragma unroll
        for (int p = 0; p < 8; p++)
            acc[j][p] = 0.f;

    float sxx[8];
    #pragma unroll
    for (int p = 0; p < 8; p++) sxx[p] = 0.f;
    float2 syy[NSLOT];
    #pragma unroll
    for (int k = 0; k < NSLOT; k++) syy[k] = make_float2(0.f, 0.f);

    // ---- prologue: stage y group 0 into buffer 0; prime x(ch0) pipeline regs
    #pragma unroll
    for (int cc = 0; cc < CPB; cc++) {
        unsigned dy = smem_u32(&sy[0][cc][0]);
        #pragma unroll
        for (int k = 0; k < NSLOT; k++)
            if (wr[k]) cp_async8(dy + (unsigned)d2of[k] * 8, yc + g2of[k], ssz[k]);
        yc += PLANE / 2;
    }
    cp_commit();
    float4 xa = make_float4(0.f, 0.f, 0.f, 0.f), xb = xa;
    if (comp) { xa = __ldg(xp); xb = __ldg(xp + 1); }
    cp_wait0();
    __syncthreads();

    // ================= group loop: 64 iterations of 4 channels =================
    #pragma unroll 1
    for (int g = 0; g < NGRP; g++) {
        const int buf = g & 1;
        const bool pf = (g + 1 < NGRP);

        if (pf) {
            #pragma unroll
            for (int cc = 0; cc < CPB; cc++) {
                unsigned dy = smem_u32(&sy[buf ^ 1][cc][0]);
                #pragma unroll
                for (int k = 0; k < NSLOT; k++)
                    if (wr[k]) cp_async8(dy + (unsigned)d2of[k] * 8,
                                         yc + g2of[k], ssz[k]);
                yc += PLANE / 2;
            }
            cp_commit();
        }

        // ---- compute 4 channels; x LDG pipelined one channel ahead
        #pragma unroll
        for (int cc = 0; cc < CPB; cc++) {
            if (comp) {
                // issue next channel's x load (clamped at the tail; redundant
                // last load is harmless and keeps the loop branch-free)
                int nidx = g * CPB + cc + 1;
                if (nidx > CCH - 1) nidx = CCH - 1;
                const float4* xq = xp + (size_t)nidx * (PLANE / 4);
                float4 na = __ldg(xq);
                float4 nb = __ldg(xq + 1);

                float xv[8] = {xa.x, xa.y, xa.z, xa.w, xb.x, xb.y, xb.z, xb.w};
                #pragma unroll
                for (int p = 0; p < 8; p++)
                    sxx[p] = fmaf(xv[p], xv[p], sxx[p]);

                const float* row = &sy[buf][cc][(ty + grp) * SMW + tx * 8];
                float4 t0 = *reinterpret_cast<const float4*>(row);
                float4 t1 = *reinterpret_cast<const float4*>(row + 4);
                float4 t2 = *reinterpret_cast<const float4*>(row + 8);
                float4 t3 = *reinterpret_cast<const float4*>(row + 12);
                float yr[16] = {t0.x, t0.y, t0.z, t0.w, t1.x, t1.y, t1.z, t1.w,
                                t2.x, t2.y, t2.z, t2.w, t3.x, t3.y, t3.z, t3.w};
                #pragma unroll
                for (int j = 0; j < 7; j++)
                    #pragma unroll
                    for (int p = 0; p < 8; p++)
                        acc[j][p] = fmaf(xv[p], yr[p + j + 1], acc[j][p]);

                xa = na; xb = nb;
            }

            // sum(y^2) readback of this thread's own staged slots (zeros where OOB)
            const float2* slab2 = reinterpret_cast<const float2*>(&sy[buf][cc][0]);
            #pragma unroll
            for (int k = 0; k < NSLOT; k++) {
                if (wr[k]) {
                    float2 v = slab2[d2of[k]];
                    syy[k].x = fmaf(v.x, v.x, syy[k].x);
                    syy[k].y = fmaf(v.y, v.y, syy[k].y);
                }
            }
        }

        cp_wait0();
        __syncthreads();
    }

    // ================= epilogue: normalize =================
    // publish per-halo-pixel sum(y^2) through slab (0,0)
    #pragma unroll
    for (int k = 0; k < NSLOT; k++)
        if (wr[k])
            reinterpret_cast<float2*>(&sy[0][0][0])[d2of[k]] = syy[k];
    __syncthreads();

    if (comp) {
        float invx[8];
        #pragma unroll
        for (int p = 0; p < 8; p++)
            invx[p] = 1.0f / fmaxf(sqrtf(sxx[p]), EPSF);

        const float* row = &sy[0][0][(ty + grp) * SMW + tx * 8];
        float inr[15];
        #pragma unroll
        for (int t = 1; t <= 14; t++)
            inr[t] = 1.0f / fmaxf(sqrtf(row[t]), EPSF);

        float* op = out + ((size_t)b * 49 + grp * 7) * PLANE
                        + (size_t)h * WW + w0 + tx * 8;
        #pragma unroll
        for (int j = 0; j < 7; j++) {
            float4 oa, ob;
            oa.x = acc[j][0] * invx[0] * inr[j + 1];
            oa.y = acc[j][1] * invx[1] * inr[j + 2];
            oa.z = acc[j][2] * invx[2] * inr[j + 3];
            oa.w = acc[j][3] * invx[3] * inr[j + 4];
            ob.x = acc[j][4] * invx[4] * inr[j + 5];
            ob.y = acc[j][5] * invx[5] * inr[j + 6];
            ob.z = acc[j][6] * invx[6] * inr[j + 7];
            ob.w = acc[j][7] * invx[7] * inr[j + 8];
            *reinterpret_cast<float4*>(op + (size_t)j * PLANE)     = oa;
            *reinterpret_cast<float4*>(op + (size_t)j * PLANE + 4) = ob;
        }
    }
}

extern "C" void kernel_launch(void* const* d_in, const int* in_sizes, int n_in,
                              void* d_out, int out_size) {
    const float* x = (const float*)d_in[0];
    const float* y = (const float*)d_in[1];
    float* out = (float*)d_out;
    int B = in_sizes[0] / (CCH * HH * WW);   // = 4
    dim3 grid(WW / TW, HH / TH, B);
    corr_kernel<<<grid, NTHREADS>>>(x, y, out);
}

// round 15
// speedup vs baseline: 2.1360x; 2.1360x over previous
#include <cuda_runtime.h>
#include <cstdint>

#define CCH 256
#define HH 256
#define WW 256
#define PLANE (HH * WW)
#define TH 4
#define TW 32
#define HALO_ROWS 10              // TH + 6
#define HALO_W2 20                // staged float2 per row (40 floats)
#define HALO_N2 (HALO_ROWS * HALO_W2)  // 200 float2 per channel slab
#define SMW 44                    // y slab row stride in floats (conflict-free padding)
#define SMW2 (SMW / 2)            // 22 float2 stride
#define SLAB (HALO_ROWS * SMW)    // 440 floats per y slab
#define XROW 36                   // x slab row stride in floats (conflict-free padding)
#define XSLAB (TH * XROW)         // 144 floats per x slab
#define CPB 4                     // channels per barrier
#define NGRP (CCH / CPB)          // 64 groups
#define NBUF 3                    // triple-buffered pipeline
#define NSLOT 2                   // ceil(200 / 128) y staging slots per thread
#define NTHREADS 128
#define EPSF 1e-12f

__device__ __forceinline__ unsigned smem_u32(const void* p) {
    return (unsigned)__cvta_generic_to_shared(p);
}
__device__ __forceinline__ void cp_async8(unsigned dst, const void* src, unsigned sz) {
    asm volatile("cp.async.ca.shared.global [%0], [%1], 8, %2;\n"
                 :: "r"(dst), "l"(src), "r"(sz));
}
__device__ __forceinline__ void cp_async16(unsigned dst, const void* src) {
    asm volatile("cp.async.ca.shared.global [%0], [%1], 16;\n"
                 :: "r"(dst), "l"(src));
}
__device__ __forceinline__ void cp_commit() {
    asm volatile("cp.async.commit_group;\n");
}
template <int N>
__device__ __forceinline__ void cp_wait() {
    asm volatile("cp.async.wait_group %0;\n" :: "n"(N));
}

__global__ __launch_bounds__(NTHREADS, 4)
void corr_kernel(const float* __restrict__ x,
                 const float* __restrict__ y,
                 float* __restrict__ out)
{
    __shared__ __align__(16) float sy[NBUF][CPB][SLAB];
    __shared__ __align__(16) float sx[NBUF][CPB][XSLAB];

    const int tid = threadIdx.x;
    const int tx  = tid & 3;          // 0..3, each owns 8 w-pixels
    const int ty  = (tid >> 2) & 3;   // 0..3
    const int grp = tid >> 4;         // 0..7: vertical offset index (7 = staging-only)
    const bool comp = (grp < 7);
    const int b   = blockIdx.z;
    const int h0  = blockIdx.y * TH;
    const int w0  = blockIdx.x * TW;
    const int h   = h0 + ty;

    // ---- y staging slots: halo gy in [h0-3, h0+6], gx in [w0-4, w0+35], even gx
    int      g2of[NSLOT];
    int      d2of[NSLOT];
    unsigned ssz[NSLOT];
    bool     wr[NSLOT];
    #pragma unroll
    for (int k = 0; k < NSLOT; k++) {
        int li = tid + k * NTHREADS;
        int r  = li / HALO_W2;
        int c2 = li - r * HALO_W2;
        int gy = h0 - 3 + r;
        int gx = w0 - 4 + 2 * c2;
        wr[k]  = li < HALO_N2;
        bool v = wr[k] && gy >= 0 && gy < HH && gx >= 0 && gx < WW;
        g2of[k] = v ? (gy * (WW / 2) + (gx >> 1)) : 0;
        d2of[k] = r * SMW2 + c2;
        ssz[k]  = v ? 8u : 0u;
    }

    // ---- x staging: threads 0..31 stage one float4 per channel (4 rows x 8 quads)
    const bool xstage = (tid < 32);
    const unsigned xdst = (unsigned)((tid >> 3) * (XROW * 4) + (tid & 7) * 16);
    const float* xsrc = x + (((size_t)b * CCH) * HH + h0 + (tid >> 3)) * WW
                          + w0 + (tid & 7) * 4;
    const float2* yc = reinterpret_cast<const float2*>(y) +
        (size_t)b * CCH * (PLANE / 2);

    float acc[7][8];
    #pragma unroll
    for (int j = 0; j < 7; j++)
        #pragma unroll
        for (int p = 0; p < 8; p++)
            acc[j][p] = 0.f;

    float sxx[8];
    #pragma unroll
    for (int p = 0; p < 8; p++) sxx[p] = 0.f;
    float2 syy[NSLOT];
    #pragma unroll
    for (int k = 0; k < NSLOT; k++) syy[k] = make_float2(0.f, 0.f);

    // ---- prologue: stage groups 0 and 1 into buffers 0 and 1 (separate commits)
    #pragma unroll
    for (int gg = 0; gg < 2; gg++) {
        #pragma unroll
        for (int cc = 0; cc < CPB; cc++) {
            unsigned dy = smem_u32(&sy[gg][cc][0]);
            #pragma unroll
            for (int k = 0; k < NSLOT; k++)
                if (wr[k]) cp_async8(dy + (unsigned)d2of[k] * 8,
                                     yc + g2of[k], ssz[k]);
            yc += PLANE / 2;
            if (xstage)
                cp_async16(smem_u32(&sx[gg][cc][0]) + xdst,
                           xsrc + (size_t)(gg * CPB + cc) * PLANE);
        }
        cp_commit();
    }
    cp_wait<1>();        // group 0 complete (group 1 may still be in flight)
    __syncthreads();

    // ================= group loop: 64 iterations of 4 channels =================
    int cur = 0;
    #pragma unroll 1
    for (int g = 0; g < NGRP; g++) {
        const bool pf2 = (g + 2 < NGRP);

        // stage group g+2 into buffer (cur+2)%3 — its readers drained at the
        // barrier that ended iteration g-1
        if (pf2) {
            int sb = cur + 2; if (sb >= NBUF) sb -= NBUF;
            const float* xs2 = xsrc + (size_t)(g + 2) * CPB * PLANE;
            #pragma unroll
            for (int cc = 0; cc < CPB; cc++) {
                unsigned dy = smem_u32(&sy[sb][cc][0]);
                #pragma unroll
                for (int k = 0; k < NSLOT; k++)
                    if (wr[k]) cp_async8(dy + (unsigned)d2of[k] * 8,
                                         yc + g2of[k], ssz[k]);
                yc += PLANE / 2;
                if (xstage)
                    cp_async16(smem_u32(&sx[sb][cc][0]) + xdst,
                               xs2 + (size_t)cc * PLANE);
            }
            cp_commit();
        }

        // ---- compute 4 channels from buffer cur (R12 body)
        #pragma unroll
        for (int cc = 0; cc < CPB; cc++) {
            if (comp) {
                const float* xr = &sx[cur][cc][ty * XROW + tx * 8];
                float4 xa = *reinterpret_cast<const float4*>(xr);
                float4 xb = *reinterpret_cast<const float4*>(xr + 4);
                float xv[8] = {xa.x, xa.y, xa.z, xa.w, xb.x, xb.y, xb.z, xb.w};
                #pragma unroll
                for (int p = 0; p < 8; p++)
                    sxx[p] = fmaf(xv[p], xv[p], sxx[p]);

                const float* row = &sy[cur][cc][(ty + grp) * SMW + tx * 8];
                float4 t0 = *reinterpret_cast<const float4*>(row);
                float4 t1 = *reinterpret_cast<const float4*>(row + 4);
                float4 t2 = *reinterpret_cast<const float4*>(row + 8);
                float4 t3 = *reinterpret_cast<const float4*>(row + 12);
                float yr[16] = {t0.x, t0.y, t0.z, t0.w, t1.x, t1.y, t1.z, t1.w,
                                t2.x, t2.y, t2.z, t2.w, t3.x, t3.y, t3.z, t3.w};
                #pragma unroll
                for (int j = 0; j < 7; j++)
                    #pragma unroll
                    for (int p = 0; p < 8; p++)
                        acc[j][p] = fmaf(xv[p], yr[p + j + 1], acc[j][p]);
            }

            // sum(y^2) readback of this thread's own staged slots (zeros where OOB)
            const float2* slab2 = reinterpret_cast<const float2*>(&sy[cur][cc][0]);
            #pragma unroll
            for (int k = 0; k < NSLOT; k++) {
                if (wr[k]) {
                    float2 v = slab2[d2of[k]];
                    syy[k].x = fmaf(v.x, v.x, syy[k].x);
                    syy[k].y = fmaf(v.y, v.y, syy[k].y);
                }
            }
        }

        // need group g+1 complete before next iteration reads it.
        // while still issuing (pf2): g+2 may stay in flight -> wait_group 1.
        // at the tail (no new issue): drain fully so g+1 is provably done.
        if (pf2) cp_wait<1>(); else cp_wait<0>();
        __syncthreads();
        cur = cur + 1; if (cur == NBUF) cur = 0;
    }

    // ================= epilogue: normalize =================
    // publish per-halo-pixel sum(y^2) through slab (0,0)
    #pragma unroll
    for (int k = 0; k < NSLOT; k++)
        if (wr[k])
            reinterpret_cast<float2*>(&sy[0][0][0])[d2of[k]] = syy[k];
    __syncthreads();

    if (comp) {
        float invx[8];
        #pragma unroll
        for (int p = 0; p < 8; p++)
            invx[p] = 1.0f / fmaxf(sqrtf(sxx[p]), EPSF);

        const float* row = &sy[0][0][(ty + grp) * SMW + tx * 8];
        float inr[15];
        #pragma unroll
        for (int t = 1; t <= 14; t++)
            inr[t] = 1.0f / fmaxf(sqrtf(row[t]), EPSF);

        float* op = out + ((size_t)b * 49 + grp * 7) * PLANE
                        + (size_t)h * WW + w0 + tx * 8;
        #pragma unroll
        for (int j = 0; j < 7; j++) {
            float4 oa, ob;
            oa.x = acc[j][0] * invx[0] * inr[j + 1];
            oa.y = acc[j][1] * invx[1] * inr[j + 2];
            oa.z = acc[j][2] * invx[2] * inr[j + 3];
            oa.w = acc[j][3] * invx[3] * inr[j + 4];
            ob.x = acc[j][4] * invx[4] * inr[j + 5];
            ob.y = acc[j][5] * invx[5] * inr[j + 6];
            ob.z = acc[j][6] * invx[6] * inr[j + 7];
            ob.w = acc[j][7] * invx[7] * inr[j + 8];
            *reinterpret_cast<float4*>(op + (size_t)j * PLANE)     = oa;
            *reinterpret_cast<float4*>(op + (size_t)j * PLANE + 4) = ob;
        }
    }
}

extern "C" void kernel_launch(void* const* d_in, const int* in_sizes, int n_in,
                              void* d_out, int out_size) {
    const float* x = (const float*)d_in[0];
    const float* y = (const float*)d_in[1];
    float* out = (float*)d_out;
    int B = in_sizes[0] / (CCH * HH * WW);   // = 4
    dim3 grid(WW / TW, HH / TH, B);
    corr_kernel<<<grid, NTHREADS>>>(x, y, out);
}

// round 16
// speedup vs baseline: 2.1521x; 1.0075x over previous
#include <cuda_runtime.h>
#include <cstdint>

#define CCH 256
#define HH 256
#define WW 256
#define PLANE (HH * WW)
#define TH 4
#define TW 32
#define HALO_ROWS 10              // TH + 6
#define HALO_W2 20                // staged float2 per row (40 floats)
#define HALO_N2 (HALO_ROWS * HALO_W2)  // 200 float2 per channel slab
#define SMW 44                    // y slab row stride in floats (conflict-free padding)
#define SMW2 (SMW / 2)            // 22 float2 stride
#define SLAB (HALO_ROWS * SMW)    // 440 floats per y slab
#define XROW 36                   // x slab row stride in floats (conflict-free padding)
#define XSLAB (TH * XROW)         // 144 floats per x slab
#define CPB 8                     // channels per barrier (static smem, R12 body)
#define NGRP (CCH / CPB)          // 32 groups
#define NSLOT 2                   // ceil(200 / 128) y staging slots per thread
#define NTHREADS 128
#define EPSF 1e-12f

__device__ __forceinline__ unsigned smem_u32(const void* p) {
    return (unsigned)__cvta_generic_to_shared(p);
}
__device__ __forceinline__ void cp_async8(unsigned dst, const void* src, unsigned sz) {
    asm volatile("cp.async.ca.shared.global [%0], [%1], 8, %2;\n"
                 :: "r"(dst), "l"(src), "r"(sz));
}
__device__ __forceinline__ void cp_async16(unsigned dst, const void* src) {
    asm volatile("cp.async.ca.shared.global [%0], [%1], 16;\n"
                 :: "r"(dst), "l"(src));
}
__device__ __forceinline__ void cp_commit() {
    asm volatile("cp.async.commit_group;\n");
}
__device__ __forceinline__ void cp_wait0() {
    asm volatile("cp.async.wait_group 0;\n");
}

__global__ __launch_bounds__(NTHREADS, 4)
void corr_kernel(const float* __restrict__ x,
                 const float* __restrict__ y,
                 float* __restrict__ out)
{
    __shared__ __align__(16) float sy[2][CPB][SLAB];
    __shared__ __align__(16) float sx[2][CPB][XSLAB];

    const int tid = threadIdx.x;
    const int tx  = tid & 3;          // 0..3, each owns 8 w-pixels
    const int ty  = (tid >> 2) & 3;   // 0..3
    const int grp = tid >> 4;         // 0..7: vertical offset index (7 = staging-only)
    const bool comp = (grp < 7);
    const int b   = blockIdx.z;
    const int h0  = blockIdx.y * TH;
    const int w0  = blockIdx.x * TW;
    const int h   = h0 + ty;

    // ---- y staging slots: halo gy in [h0-3, h0+6], gx in [w0-4, w0+35], even gx
    int      g2of[NSLOT];   // global float2 offset
    int      d2of[NSLOT];   // slab float2 offset (stride 22 float2 per row)
    unsigned ssz[NSLOT];
    bool     wr[NSLOT];
    #pragma unroll
    for (int k = 0; k < NSLOT; k++) {
        int li = tid + k * NTHREADS;
        int r  = li / HALO_W2;
        int c2 = li - r * HALO_W2;
        int gy = h0 - 3 + r;
        int gx = w0 - 4 + 2 * c2;
        wr[k]  = li < HALO_N2;
        bool v = wr[k] && gy >= 0 && gy < HH && gx >= 0 && gx < WW;
        g2of[k] = v ? (gy * (WW / 2) + (gx >> 1)) : 0;
        d2of[k] = r * SMW2 + c2;
        ssz[k]  = v ? 8u : 0u;
    }

    // ---- x staging: threads 0..31 stage one float4 per channel (4 rows x 8 quads)
    const bool xstage = (tid < 32);
    const unsigned xdst = (unsigned)((tid >> 3) * (XROW * 4) + (tid & 7) * 16);
    const float* xsrc = x + (((size_t)b * CCH) * HH + h0 + (tid >> 3)) * WW
                          + w0 + (tid & 7) * 4;
    const float2* yc = reinterpret_cast<const float2*>(y) +
        (size_t)b * CCH * (PLANE / 2);

    float acc[7][8];
    #pragma unroll
    for (int j = 0; j < 7; j++)
        #pragma unroll
        for (int p = 0; p < 8; p++)
            acc[j][p] = 0.f;

    float sxx[8];
    #pragma unroll
    for (int p = 0; p < 8; p++) sxx[p] = 0.f;
    float2 syy[NSLOT];
    #pragma unroll
    for (int k = 0; k < NSLOT; k++) syy[k] = make_float2(0.f, 0.f);

    // ---- prologue: stage group 0 (channels 0..7) into buffer 0
    #pragma unroll
    for (int cc = 0; cc < CPB; cc++) {
        unsigned dy = smem_u32(&sy[0][cc][0]);
        #pragma unroll
        for (int k = 0; k < NSLOT; k++)
            if (wr[k]) cp_async8(dy + (unsigned)d2of[k] * 8, yc + g2of[k], ssz[k]);
        yc += PLANE / 2;
        if (xstage)
            cp_async16(smem_u32(&sx[0][cc][0]) + xdst, xsrc + (size_t)cc * PLANE);
    }
    cp_commit();
    cp_wait0();
    __syncthreads();

    // ================= group loop: 32 iterations of 8 channels =================
    #pragma unroll 1
    for (int g = 0; g < NGRP; g++) {
        const int buf = g & 1;
        const bool pf = (g + 1 < NGRP);

        if (pf) {
            #pragma unroll
            for (int cc = 0; cc < CPB; cc++) {
                unsigned dy = smem_u32(&sy[buf ^ 1][cc][0]);
                #pragma unroll
                for (int k = 0; k < NSLOT; k++)
                    if (wr[k]) cp_async8(dy + (unsigned)d2of[k] * 8,
                                         yc + g2of[k], ssz[k]);
                yc += PLANE / 2;
                if (xstage)
                    cp_async16(smem_u32(&sx[buf ^ 1][cc][0]) + xdst,
                               xsrc + (size_t)((g + 1) * CPB + cc) * PLANE);
            }
            cp_commit();
        }

        // ---- compute 8 channels from current buffers (R12 body)
        #pragma unroll
        for (int cc = 0; cc < CPB; cc++) {
            if (comp) {
                const float* xr = &sx[buf][cc][ty * XROW + tx * 8];
                float4 xa = *reinterpret_cast<const float4*>(xr);
                float4 xb = *reinterpret_cast<const float4*>(xr + 4);
                float xv[8] = {xa.x, xa.y, xa.z, xa.w, xb.x, xb.y, xb.z, xb.w};
                #pragma unroll
                for (int p = 0; p < 8; p++)
                    sxx[p] = fmaf(xv[p], xv[p], sxx[p]);

                const float* row = &sy[buf][cc][(ty + grp) * SMW + tx * 8];
                float4 t0 = *reinterpret_cast<const float4*>(row);
                float4 t1 = *reinterpret_cast<const float4*>(row + 4);
                float4 t2 = *reinterpret_cast<const float4*>(row + 8);
                float4 t3 = *reinterpret_cast<const float4*>(row + 12);
                float yr[16] = {t0.x, t0.y, t0.z, t0.w, t1.x, t1.y, t1.z, t1.w,
                                t2.x, t2.y, t2.z, t2.w, t3.x, t3.y, t3.z, t3.w};
                #pragma unroll
                for (int j = 0; j < 7; j++)
                    #pragma unroll
                    for (int p = 0; p < 8; p++)
                        acc[j][p] = fmaf(xv[p], yr[p + j + 1], acc[j][p]);
            }

            // sum(y^2) readback of this thread's own staged slots (zeros where OOB)
            const float2* slab2 = reinterpret_cast<const float2*>(&sy[buf][cc][0]);
            #pragma unroll
            for (int k = 0; k < NSLOT; k++) {
                if (wr[k]) {
                    float2 v = slab2[d2of[k]];
                    syy[k].x = fmaf(v.x, v.x, syy[k].x);
                    syy[k].y = fmaf(v.y, v.y, syy[k].y);
                }
            }
        }

        cp_wait0();
        __syncthreads();
    }

    // ================= epilogue: normalize =================
    // publish per-halo-pixel sum(y^2) through slab (0,0)
    #pragma unroll
    for (int k = 0; k < NSLOT; k++)
        if (wr[k])
            reinterpret_cast<float2*>(&sy[0][0][0])[d2of[k]] = syy[k];
    __syncthreads();

    if (comp) {
        float invx[8];
        #pragma unroll
        for (int p = 0; p < 8; p++)
            invx[p] = 1.0f / fmaxf(sqrtf(sxx[p]), EPSF);

        const float* row = &sy[0][0][(ty + grp) * SMW + tx * 8];
        float inr[15];
        #pragma unroll
        for (int t = 1; t <= 14; t++)
            inr[t] = 1.0f / fmaxf(sqrtf(row[t]), EPSF);

        float* op = out + ((size_t)b * 49 + grp * 7) * PLANE
                        + (size_t)h * WW + w0 + tx * 8;
        #pragma unroll
        for (int j = 0; j < 7; j++) {
            float4 oa, ob;
            oa.x = acc[j][0] * invx[0] * inr[j + 1];
            oa.y = acc[j][1] * invx[1] * inr[j + 2];
            oa.z = acc[j][2] * invx[2] * inr[j + 3];
            oa.w = acc[j][3] * invx[3] * inr[j + 4];
            ob.x = acc[j][4] * invx[4] * inr[j + 5];
            ob.y = acc[j][5] * invx[5] * inr[j + 6];
            ob.z = acc[j][6] * invx[6] * inr[j + 7];
            ob.w = acc[j][7] * invx[7] * inr[j + 8];
            *reinterpret_cast<float4*>(op + (size_t)j * PLANE)     = oa;
            *reinterpret_cast<float4*>(op + (size_t)j * PLANE + 4) = ob;
        }
    }
}

extern "C" void kernel_launch(void* const* d_in, const int* in_sizes, int n_in,
                              void* d_out, int out_size) {
    const float* x = (const float*)d_in[0];
    const float* y = (const float*)d_in[1];
    float* out = (float*)d_out;
    int B = in_sizes[0] / (CCH * HH * WW);   // = 4
    dim3 grid(WW / TW, HH / TH, B);
    corr_kernel<<<grid, NTHREADS>>>(x, y, out);
}